// round 1
// baseline (speedup 1.0000x reference)
#include <cuda_runtime.h>
#include <math.h>

#define N_SMP 32
#define CH    128
#define HWPX  4096

// ---------------- device scratch (no allocations allowed) ----------------
__device__ float g_wmod[N_SMP * CH * CH * 9];   // 18.9 MB
__device__ float g_y[N_SMP * CH * HWPX];        // 67 MB conv output
__device__ float g_z[N_SMP * CH * HWPX];        // 67 MB normalized (layer2 input)
__device__ float g_stats[N_SMP * CH * 2];       // sum / sumsq
__device__ float g_bias[2][N_SMP * CH];
__device__ float g_adg[2][N_SMP * CH];
__device__ float g_adb[2][N_SMP * CH];

// ---------------- small per-sample vectors: bias, adain gamma/beta -------
__global__ void modvec_kernel(const float* __restrict__ task, const float* __restrict__ style,
    const float* __restrict__ b1, const float* __restrict__ tb1w, const float* __restrict__ tb1b,
    const float* __restrict__ ad1w, const float* __restrict__ ad1b,
    const float* __restrict__ b2, const float* __restrict__ tb2w, const float* __restrict__ tb2b,
    const float* __restrict__ ad2w, const float* __restrict__ ad2b)
{
    __shared__ float ts[512], ss[512];
    const int n = blockIdx.x;
    const int co = threadIdx.x;   // 128 threads
    for (int k = co; k < 512; k += 128) { ts[k] = task[n*512+k]; ss[k] = style[n*512+k]; }
    __syncthreads();
    float a0=0.f,a1=0.f,a2=0.f,a3=0.f,a4=0.f,a5=0.f;
    for (int k = 0; k < 512; k++) {
        float t = ts[k], s = ss[k];
        a0 = fmaf(tb1w[co*512+k],       t, a0);
        a1 = fmaf(ad1w[co*512+k],       s, a1);
        a2 = fmaf(ad1w[(co+128)*512+k], s, a2);
        a3 = fmaf(tb2w[co*512+k],       t, a3);
        a4 = fmaf(ad2w[co*512+k],       s, a4);
        a5 = fmaf(ad2w[(co+128)*512+k], s, a5);
    }
    const float se = 0.0625f;  // sqrt(2/512)
    g_bias[0][n*128+co] = b1[co] + a0*se + tb1b[co];
    g_adg [0][n*128+co] = a1*se + ad1b[co];
    g_adb [0][n*128+co] = a2*se + ad1b[co+128];
    g_bias[1][n*128+co] = b2[co] + a3*se + tb2b[co];
    g_adg [1][n*128+co] = a4*se + ad2b[co];
    g_adb [1][n*128+co] = a5*se + ad2b[co+128];
}

// ---------------- gamma/beta GEMM fused with Wmod build ------------------
// G[j, n] = dot(tw[j,:], task[n,:]),  j in [0, 32768)  (j = (co*128+ci)*2 + p)
// Wmod[n,co,ci,k] = (W[co,ci,k]*gamma + beta) * sqrt(2/1152)
#define GB_JT 64
#define GB_KC 16
__global__ __launch_bounds__(128)
void gemm_wmod_kernel(const float* __restrict__ task, const float* __restrict__ tw,
                      const float* __restrict__ tb,   const float* __restrict__ Wt)
{
    __shared__ float As[GB_KC][GB_JT];
    __shared__ float Bs[GB_KC][32];
    const int tid = threadIdx.x;
    const int jb  = blockIdx.x * GB_JT;
    const int jg  = tid & 15;   // 4 j-rows each
    const int ng  = tid >> 4;   // 4 n each
    float acc[4][4] = {};

    for (int k0 = 0; k0 < 512; k0 += GB_KC) {
        #pragma unroll
        for (int t = 0; t < 2; t++) {
            int li  = tid*2 + t;          // 0..255
            int row = li >> 2;            // 0..63
            int kq  = (li & 3) * 4;
            float4 v = *(const float4*)(tw + (size_t)(jb + row)*512 + k0 + kq);
            As[kq+0][row] = v.x; As[kq+1][row] = v.y; As[kq+2][row] = v.z; As[kq+3][row] = v.w;
        }
        {
            int nn = tid >> 2;            // 0..31
            int kq = (tid & 3) * 4;
            float4 v = *(const float4*)(task + (size_t)nn*512 + k0 + kq);
            Bs[kq+0][nn] = v.x; Bs[kq+1][nn] = v.y; Bs[kq+2][nn] = v.z; Bs[kq+3][nn] = v.w;
        }
        __syncthreads();
        #pragma unroll
        for (int k = 0; k < GB_KC; k++) {
            float4 a = *(const float4*)&As[k][jg*4];
            float4 b = *(const float4*)&Bs[k][ng*4];
            float av[4] = {a.x,a.y,a.z,a.w};
            float bv[4] = {b.x,b.y,b.z,b.w};
            #pragma unroll
            for (int i = 0; i < 4; i++)
                #pragma unroll
                for (int j = 0; j < 4; j++)
                    acc[i][j] = fmaf(av[i], bv[j], acc[i][j]);
        }
        __syncthreads();
    }

    const float se  = 0.0625f;            // sqrt(2/512)
    const float swm = 1.0f/24.0f;         // sqrt(2/1152)
    const int co = jb >> 8;               // 256 j per co, tile never straddles
    #pragma unroll
    for (int i = 0; i < 4; i += 2) {
        int jg4  = jb + jg*4 + i;         // even -> gamma row, +1 -> beta row
        int ci   = (jg4 & 255) >> 1;
        float tbg = tb[jg4], tbb_ = tb[jg4+1];
        const float* wsrc = Wt + ((size_t)co*128 + ci)*9;
        float wk[9];
        #pragma unroll
        for (int k = 0; k < 9; k++) wk[k] = wsrc[k];
        #pragma unroll
        for (int nn = 0; nn < 4; nn++) {
            int n = ng*4 + nn;
            float g  = acc[i][nn]  * se + tbg;
            float be = acc[i+1][nn]* se + tbb_;
            float* wdst = g_wmod + (((size_t)n*128 + co)*128 + ci)*9;
            #pragma unroll
            for (int k = 0; k < 9; k++) wdst[k] = (wk[k]*g + be) * swm;
        }
    }
}

// ---------------- stats zero --------------------------------------------
__global__ void zero_stats_kernel() {
    int i = blockIdx.x * blockDim.x + threadIdx.x;
    if (i < N_SMP*CH*2) g_stats[i] = 0.f;
}

// ---------------- main conv: modulated 3x3 + bias + noise + leaky + stats
#define CIC 8
__global__ __launch_bounds__(256, 2)
void conv_kernel(const float* __restrict__ xin_p, int in_is_z, int layer,
                 const float* __restrict__ noise, const float* __restrict__ nzw)
{
    __shared__ float xs[CIC][18][19];     // 19-pad: breaks 4-way LDS conflicts
    __shared__ float ws[CIC][9][32];
    const int tid = threadIdx.x;
    const int sp  = blockIdx.x;           // 0..15 spatial 16x16 tiles
    const int cob = blockIdx.y * 32;
    const int n   = blockIdx.z;
    const int ty0 = (sp >> 2) * 16;
    const int tx0 = (sp &  3) * 16;
    const int cog = tid >> 5;             // warp id = co group
    const int co0 = cog * 4;
    const int lsp = tid & 31;
    const int ry0 = (lsp >> 2) * 2;
    const int cx0 = (lsp &  3) * 4;

    const float* xin = in_is_z ? g_z : xin_p;
    const float* xn  = xin + (size_t)n * CH * HWPX;

    float acc[4][2][4] = {};

    for (int cb = 0; cb < CH; cb += CIC) {
        for (int idx = tid; idx < CIC*18*18; idx += 256) {
            int cc  = idx / 324;
            int rem = idx - cc*324;
            int r   = rem / 18, c = rem - r*18;
            int gy  = ty0 - 1 + r, gx = tx0 - 1 + c;
            float v = 0.f;
            if ((unsigned)gy < 64u && (unsigned)gx < 64u)
                v = xn[(size_t)(cb+cc)*HWPX + gy*64 + gx];
            xs[cc][r][c] = v;
        }
        for (int idx = tid; idx < 32*CIC*9; idx += 256) {
            int co  = idx / 72;
            int rem = idx - co*72;
            int cc  = rem / 9, k = rem - cc*9;
            ws[cc][k][co] = g_wmod[(((size_t)n*128 + cob+co)*128 + cb+cc)*9 + k];
        }
        __syncthreads();
        #pragma unroll
        for (int cc = 0; cc < CIC; cc++) {
            float xr[4][6];
            #pragma unroll
            for (int r = 0; r < 4; r++)
                #pragma unroll
                for (int c = 0; c < 6; c++)
                    xr[r][c] = xs[cc][ry0 + r][cx0 + c];
            #pragma unroll
            for (int ky = 0; ky < 3; ky++)
                #pragma unroll
                for (int kx = 0; kx < 3; kx++) {
                    float4 w4 = *(const float4*)&ws[cc][ky*3+kx][co0];
                    float wv[4] = {w4.x, w4.y, w4.z, w4.w};
                    #pragma unroll
                    for (int o = 0; o < 4; o++)
                        #pragma unroll
                        for (int r = 0; r < 2; r++)
                            #pragma unroll
                            for (int c = 0; c < 4; c++)
                                acc[o][r][c] = fmaf(wv[o], xr[r+ky][c+kx], acc[o][r][c]);
                }
        }
        __syncthreads();
    }

    // epilogue: bias + noise + leaky relu + store + channel stats
    const float nzs = 0.125f;  // sqrt(2/128)
    float nzv[2][4];
    #pragma unroll
    for (int r = 0; r < 2; r++)
        #pragma unroll
        for (int c = 0; c < 4; c++) {
            int gy = ty0 + ry0 + r, gx = tx0 + cx0 + c;
            nzv[r][c] = noise[(size_t)n*HWPX + gy*64 + gx];
        }

    float psum[4], psq[4];
    #pragma unroll
    for (int o = 0; o < 4; o++) {
        int co = cob + co0 + o;
        float bi = g_bias[layer][n*128 + co];
        float nw = nzw[co] * nzs;
        psum[o] = 0.f; psq[o] = 0.f;
        #pragma unroll
        for (int r = 0; r < 2; r++)
            #pragma unroll
            for (int c = 0; c < 4; c++) {
                float v = acc[o][r][c] + bi + nw * nzv[r][c];
                v = (v > 0.f) ? v : 0.2f * v;
                int gy = ty0 + ry0 + r, gx = tx0 + cx0 + c;
                g_y[((size_t)n*128 + co)*HWPX + gy*64 + gx] = v;
                psum[o] += v; psq[o] += v*v;
            }
    }
    #pragma unroll
    for (int off = 16; off; off >>= 1) {
        #pragma unroll
        for (int o = 0; o < 4; o++) {
            psum[o] += __shfl_xor_sync(0xffffffffu, psum[o], off);
            psq [o] += __shfl_xor_sync(0xffffffffu, psq [o], off);
        }
    }
    if ((tid & 31) == 0) {
        #pragma unroll
        for (int o = 0; o < 4; o++) {
            int co = cob + co0 + o;
            atomicAdd(&g_stats[(n*128+co)*2+0], psum[o]);
            atomicAdd(&g_stats[(n*128+co)*2+1], psq[o]);
        }
    }
}

// ---------------- AdaIN -------------------------------------------------
__global__ void adain_kernel(int layer, int out_to_z, float* __restrict__ dout)
{
    const int nc = blockIdx.y;                    // n*128+co
    const int i4 = blockIdx.x * blockDim.x + threadIdx.x;  // 1024 float4s
    float mu  = g_stats[nc*2]   * (1.f/4096.f);
    float var = g_stats[nc*2+1] * (1.f/4096.f) - mu*mu;
    var = fmaxf(var, 0.f);
    float inv = rsqrtf(var + 1e-5f);
    float g = g_adg[layer][nc] * inv;
    float b = g_adb[layer][nc] - g * mu;
    const float4* yin = (const float4*)(g_y + (size_t)nc * HWPX);
    float4 v = yin[i4];
    float4 o;
    o.x = fmaf(g, v.x, b); o.y = fmaf(g, v.y, b);
    o.z = fmaf(g, v.z, b); o.w = fmaf(g, v.w, b);
    float* outp = out_to_z ? g_z : dout;
    ((float4*)(outp + (size_t)nc * HWPX))[i4] = o;
}

// ---------------- launch --------------------------------------------------
extern "C" void kernel_launch(void* const* d_in, const int* in_sizes, int n_in,
                              void* d_out, int out_size)
{
    const float* x     = (const float*)d_in[0];
    const float* style = (const float*)d_in[1];
    const float* noise = (const float*)d_in[2];
    const float* task  = (const float*)d_in[3];
    const float* W1    = (const float*)d_in[4];
    const float* b1    = (const float*)d_in[5];
    const float* t1w   = (const float*)d_in[6];
    const float* t1b   = (const float*)d_in[7];
    const float* tb1w  = (const float*)d_in[8];
    const float* tb1b  = (const float*)d_in[9];
    const float* nz1   = (const float*)d_in[10];
    const float* ad1w  = (const float*)d_in[11];
    const float* ad1b  = (const float*)d_in[12];
    const float* W2    = (const float*)d_in[13];
    const float* b2    = (const float*)d_in[14];
    const float* t2w   = (const float*)d_in[15];
    const float* t2b   = (const float*)d_in[16];
    const float* tb2w  = (const float*)d_in[17];
    const float* tb2b  = (const float*)d_in[18];
    const float* nz2   = (const float*)d_in[19];
    const float* ad2w  = (const float*)d_in[20];
    const float* ad2b  = (const float*)d_in[21];
    float* out = (float*)d_out;

    modvec_kernel<<<32, 128>>>(task, style, b1, tb1w, tb1b, ad1w, ad1b,
                               b2, tb2w, tb2b, ad2w, ad2b);

    // ---- layer 1 ----
    gemm_wmod_kernel<<<512, 128>>>(task, t1w, t1b, W1);
    zero_stats_kernel<<<8, 1024>>>();
    conv_kernel<<<dim3(16, 4, N_SMP), 256>>>(x, 0, 0, noise, nz1);
    adain_kernel<<<dim3(4, 4096), 256>>>(0, 1, out);

    // ---- layer 2 ----
    gemm_wmod_kernel<<<512, 128>>>(task, t2w, t2b, W2);
    zero_stats_kernel<<<8, 1024>>>();
    conv_kernel<<<dim3(16, 4, N_SMP), 256>>>(nullptr, 1, 1, noise, nz2);
    adain_kernel<<<dim3(4, 4096), 256>>>(1, 0, out);
}